// round 1
// baseline (speedup 1.0000x reference)
#include <cuda_runtime.h>
#include <cuda_bf16.h>
#include <math.h>

// Problem constants: B=4, T=2048, C=1024, H=16, D=64
#define BB 4
#define TT 2048
#define CC 1024
#define HH 16
#define DD 64
#define MM (BB*TT)        // 8192
#define C3 (3*CC)         // 3072

// ------------------------------------------------------------------
// Scratch (static device arrays; no allocation allowed)
// ------------------------------------------------------------------
__device__ float g_qkv[(size_t)BB*TT*C3];       // [B,T,3C]
__device__ float g_q[(size_t)BB*HH*TT*DD];      // [B,H,T,D] roped
__device__ float g_k[(size_t)BB*HH*TT*DD];      // [B,H,T,D] roped
__device__ float g_v[(size_t)BB*HH*TT*DD];      // [B,H,T,D]
__device__ float g_y[(size_t)BB*TT*CC];         // attention out [B,T,C]

// ------------------------------------------------------------------
// SGEMM: C[M,N] = A[M,K] @ B[K,N], all row-major fp32.
// 64x64 block tile, BK=16, 256 threads, 4x4 per thread.
// Assumes M%64==0, N%64==0, K%16==0 (true for our shapes).
// ------------------------------------------------------------------
#define GBM 64
#define GBN 64
#define GBK 16

__global__ __launch_bounds__(256) void sgemm64(
    const float* __restrict__ A, const float* __restrict__ B,
    float* __restrict__ C, int M, int N, int K)
{
    __shared__ float As[GBK][GBM];  // transposed A tile
    __shared__ float Bs[GBK][GBN];

    const int tid = threadIdx.x;
    const int tx = tid & 15;        // 0..15
    const int ty = tid >> 4;        // 0..15
    const int row0 = blockIdx.y * GBM;
    const int col0 = blockIdx.x * GBN;

    // A-load mapping: one float4 per thread
    const int arow = tid >> 2;            // 0..63
    const int ac   = (tid & 3) << 2;      // 0,4,8,12
    // B-load mapping: one float4 per thread
    const int brow = tid >> 4;            // 0..15
    const int bc   = (tid & 15) << 2;     // 0..60

    float acc[4][4];
    #pragma unroll
    for (int i = 0; i < 4; i++)
        #pragma unroll
        for (int j = 0; j < 4; j++) acc[i][j] = 0.f;

    const float* Aptr = A + (size_t)(row0 + arow) * K;
    const float* Bptr = B + col0;

    for (int k0 = 0; k0 < K; k0 += GBK) {
        float4 a4 = *(const float4*)(Aptr + k0 + ac);
        As[ac + 0][arow] = a4.x;
        As[ac + 1][arow] = a4.y;
        As[ac + 2][arow] = a4.z;
        As[ac + 3][arow] = a4.w;
        float4 b4 = *(const float4*)(Bptr + (size_t)(k0 + brow) * N + bc);
        *(float4*)&Bs[brow][bc] = b4;
        __syncthreads();

        #pragma unroll
        for (int kk = 0; kk < GBK; kk++) {
            float4 av = *(const float4*)&As[kk][ty << 2];
            float4 bv = *(const float4*)&Bs[kk][tx << 2];
            float ar[4] = {av.x, av.y, av.z, av.w};
            float br[4] = {bv.x, bv.y, bv.z, bv.w};
            #pragma unroll
            for (int i = 0; i < 4; i++)
                #pragma unroll
                for (int j = 0; j < 4; j++)
                    acc[i][j] += ar[i] * br[j];
        }
        __syncthreads();
    }

    #pragma unroll
    for (int i = 0; i < 4; i++) {
        float4 o = make_float4(acc[i][0], acc[i][1], acc[i][2], acc[i][3]);
        *(float4*)(C + (size_t)(row0 + (ty << 2) + i) * N + col0 + (tx << 2)) = o;
    }
}

// ------------------------------------------------------------------
// RoPE + transpose: qkv[B,T,3C] -> q,k,v[B,H,T,D] (rope on q,k)
// ------------------------------------------------------------------
__global__ __launch_bounds__(256) void rope_split_kernel()
{
    const long long idx = (long long)blockIdx.x * blockDim.x + threadIdx.x;
    if (idx >= (long long)BB * HH * TT * DD) return;

    const int d = (int)(idx & 63);
    const int t = (int)((idx >> 6) & 2047);
    const int h = (int)((idx >> 17) & 15);
    const int b = (int)(idx >> 21);

    const size_t base = ((size_t)(b * TT + t)) * C3 + h * DD;
    const int d2 = d ^ 32;

    const float qv = g_qkv[base + d];
    const float qp = g_qkv[base + d2];
    const float kv = g_qkv[base + CC + d];
    const float kp = g_qkv[base + CC + d2];
    const float vv = g_qkv[base + 2 * CC + d];

    // rotate_half(x)[d] = d<32 ? -x[d+32] : x[d-32]
    const float qrot = (d < 32) ? -qp : qp;
    const float krot = (d < 32) ? -kp : kp;

    const int i = d & 31;
    // inv_freq = 10000^(-i/32), computed like numpy (fp32-rounded angle)
    const float invf = (float)exp(-(double)i / 32.0 * 9.210340371976184);
    const float angle = (float)t * invf;
    const double da = (double)angle;
    const float cs = (float)cos(da);
    const float sn = (float)sin(da);

    const size_t oidx = (((size_t)(b * HH + h)) * TT + t) * DD + d;
    g_q[oidx] = qv * cs + qrot * sn;
    g_k[oidx] = kv * cs + krot * sn;
    g_v[oidx] = vv;
}

// ------------------------------------------------------------------
// Flash attention (fp32, online softmax), causal.
// Block: 256 threads. One (b,h) head and a 64-query tile per block.
// Thread (r = tid/4, g = tid%4): 16 score cols / 16 output dims.
// ------------------------------------------------------------------
#define SSTR 68   // smem row stride (floats), odd-ish to avoid conflicts, 16B aligned

__global__ __launch_bounds__(256) void attn_kernel(
    const float* __restrict__ Q, const float* __restrict__ K,
    const float* __restrict__ V, float* __restrict__ Y)
{
    extern __shared__ float sm[];
    float* Qs = sm;                   // [64][SSTR]  Q[r][d]
    float* Kt = sm + 64 * SSTR;       // [64][SSTR]  K^T[d][j]
    float* Vs = Kt + 64 * SSTR;       // [64][SSTR]  V[j][d]
    float* Ps = Vs + 64 * SSTR;       // [64][SSTR]  P[r][j]

    const int tid = threadIdx.x;
    const int qt = blockIdx.x;        // 0..31
    const int bh = blockIdx.y;        // 0..63
    const int q0 = qt * 64;
    const int b = bh >> 4, h = bh & 15;

    const float* Qb = Q + (size_t)bh * TT * DD;
    const float* Kb = K + (size_t)bh * TT * DD;
    const float* Vb = V + (size_t)bh * TT * DD;

    const int r = tid >> 2;
    const int g = tid & 3;

    // Load Q tile (4 float4 per thread)
    #pragma unroll
    for (int it = 0; it < 4; it++) {
        int lin = tid + it * 256;
        int row = lin >> 4;
        int c4 = (lin & 15) << 2;
        float4 v = *(const float4*)(Qb + (size_t)(q0 + row) * DD + c4);
        *(float4*)(Qs + row * SSTR + c4) = v;
    }

    float m_old = -INFINITY, l = 0.f;
    float acc[16];
    #pragma unroll
    for (int i = 0; i < 16; i++) acc[i] = 0.f;

    for (int kt = 0; kt <= qt; kt++) {
        const int k0 = kt * 64;
        __syncthreads();  // protect smem vs previous iteration's PV reads

        // Load K (transposed into Kt) and V
        #pragma unroll
        for (int it = 0; it < 4; it++) {
            int lin = tid + it * 256;
            int row = lin >> 4;
            int c4 = (lin & 15) << 2;
            float4 kv = *(const float4*)(Kb + (size_t)(k0 + row) * DD + c4);
            Kt[(c4 + 0) * SSTR + row] = kv.x;
            Kt[(c4 + 1) * SSTR + row] = kv.y;
            Kt[(c4 + 2) * SSTR + row] = kv.z;
            Kt[(c4 + 3) * SSTR + row] = kv.w;
            float4 vv = *(const float4*)(Vb + (size_t)(k0 + row) * DD + c4);
            *(float4*)(Vs + row * SSTR + c4) = vv;
        }
        __syncthreads();

        // S = Q K^T  (this thread: 16 cols  [g*16, g*16+16) )
        float s[16];
        #pragma unroll
        for (int i = 0; i < 16; i++) s[i] = 0.f;
        const float* qrow = Qs + r * SSTR;
        #pragma unroll 8
        for (int d = 0; d < 64; d++) {
            float qv = qrow[d];
            const float4* kp = (const float4*)(Kt + d * SSTR + g * 16);
            #pragma unroll
            for (int m4 = 0; m4 < 4; m4++) {
                float4 kv = kp[m4];
                s[m4 * 4 + 0] += qv * kv.x;
                s[m4 * 4 + 1] += qv * kv.y;
                s[m4 * 4 + 2] += qv * kv.z;
                s[m4 * 4 + 3] += qv * kv.w;
            }
        }

        // scale + causal mask (diagonal tile only) + row max
        float mt = -INFINITY;
        const int qi = q0 + r;
        if (kt == qt) {
            #pragma unroll
            for (int j = 0; j < 16; j++) {
                int kj = k0 + g * 16 + j;
                float sv = s[j] * 0.125f;
                s[j] = (kj <= qi) ? sv : -INFINITY;
                mt = fmaxf(mt, s[j]);
            }
        } else {
            #pragma unroll
            for (int j = 0; j < 16; j++) {
                s[j] *= 0.125f;
                mt = fmaxf(mt, s[j]);
            }
        }
        mt = fmaxf(mt, __shfl_xor_sync(0xffffffffu, mt, 1));
        mt = fmaxf(mt, __shfl_xor_sync(0xffffffffu, mt, 2));

        const float m_new = fmaxf(m_old, mt);
        float lsum = 0.f;
        #pragma unroll
        for (int j = 0; j < 16; j++) {
            float p = __expf(s[j] - m_new);
            s[j] = p;
            lsum += p;
        }
        lsum += __shfl_xor_sync(0xffffffffu, lsum, 1);
        lsum += __shfl_xor_sync(0xffffffffu, lsum, 2);
        const float alpha = __expf(m_old - m_new);
        l = l * alpha + lsum;
        m_old = m_new;

        // Stage P tile
        float* prow = Ps + r * SSTR + g * 16;
        #pragma unroll
        for (int m4 = 0; m4 < 4; m4++) {
            float4 pv = make_float4(s[m4*4], s[m4*4+1], s[m4*4+2], s[m4*4+3]);
            *(float4*)(prow + m4 * 4) = pv;
        }
        #pragma unroll
        for (int i = 0; i < 16; i++) acc[i] *= alpha;
        __syncthreads();

        // O += P @ V  (this thread: dims [g*16, g*16+16) )
        const float* prow2 = Ps + r * SSTR;
        #pragma unroll 4
        for (int j = 0; j < 64; j++) {
            float p = prow2[j];
            const float4* vp = (const float4*)(Vs + j * SSTR + g * 16);
            #pragma unroll
            for (int m4 = 0; m4 < 4; m4++) {
                float4 vv = vp[m4];
                acc[m4 * 4 + 0] += p * vv.x;
                acc[m4 * 4 + 1] += p * vv.y;
                acc[m4 * 4 + 2] += p * vv.z;
                acc[m4 * 4 + 3] += p * vv.w;
            }
        }
    }

    // Epilogue: normalize and write [B,T,C] layout
    const float inv = 1.f / l;
    const int t = q0 + r;
    float* outp = g_y + ((size_t)(b * TT + t)) * CC + h * DD + g * 16;
    #pragma unroll
    for (int m4 = 0; m4 < 4; m4++) {
        float4 o = make_float4(acc[m4*4] * inv, acc[m4*4+1] * inv,
                               acc[m4*4+2] * inv, acc[m4*4+3] * inv);
        *(float4*)(outp + m4 * 4) = o;
    }
    (void)Y;
}

// ------------------------------------------------------------------
// Launch
// ------------------------------------------------------------------
extern "C" void kernel_launch(void* const* d_in, const int* in_sizes, int n_in,
                              void* d_out, int out_size)
{
    const float* x      = (const float*)d_in[0];  // [4,2048,1024]
    const float* w_qkv  = (const float*)d_in[1];  // [1024,3072]
    const float* w_proj = (const float*)d_in[2];  // [1024,1024]
    float* out = (float*)d_out;                   // [4,2048,1024]

    float *p_qkv, *p_q, *p_k, *p_v, *p_y;
    cudaGetSymbolAddress((void**)&p_qkv, g_qkv);
    cudaGetSymbolAddress((void**)&p_q, g_q);
    cudaGetSymbolAddress((void**)&p_k, g_k);
    cudaGetSymbolAddress((void**)&p_v, g_v);
    cudaGetSymbolAddress((void**)&p_y, g_y);

    // 1. qkv = x @ w_qkv   (8192 x 3072 x 1024)
    {
        dim3 grid(C3 / GBN, MM / GBM);
        sgemm64<<<grid, 256>>>(x, w_qkv, p_qkv, MM, C3, CC);
    }

    // 2. rope + split into [B,H,T,D]
    {
        long long n = (long long)BB * HH * TT * DD;
        int blocks = (int)((n + 255) / 256);
        rope_split_kernel<<<blocks, 256>>>();
    }

    // 3. causal flash attention
    {
        const int smem = 4 * 64 * SSTR * sizeof(float);  // 69632 B
        cudaFuncSetAttribute(attn_kernel,
                             cudaFuncAttributeMaxDynamicSharedMemorySize, smem);
        dim3 grid(TT / 64, BB * HH);
        attn_kernel<<<grid, 256, smem>>>(p_q, p_k, p_v, p_y);
    }

    // 4. out = y @ w_proj   (8192 x 1024 x 1024)
    {
        dim3 grid(CC / GBN, MM / GBM);
        sgemm64<<<grid, 256>>>(p_y, w_proj, out, MM, CC, CC);
    }
}

// round 2
// speedup vs baseline: 2.2021x; 2.2021x over previous
#include <cuda_runtime.h>
#include <cuda_bf16.h>
#include <math.h>

// Problem constants: B=4, T=2048, C=1024, H=16, D=64
#define BB 4
#define TT 2048
#define CC 1024
#define HH 16
#define DD 64
#define MM (BB*TT)        // 8192
#define C3 (3*CC)         // 3072

// ------------------------------------------------------------------
// Scratch
// ------------------------------------------------------------------
__device__ float g_qkv[(size_t)BB*TT*C3];       // [B,T,3C]
__device__ float g_q[(size_t)BB*HH*TT*DD];      // [B,H,T,D] roped
__device__ float g_k[(size_t)BB*HH*TT*DD];      // [B,H,T,D] roped
__device__ float g_v[(size_t)BB*HH*TT*DD];      // [B,H,T,D]
__device__ float g_y[(size_t)BB*TT*CC];         // attention out [B,T,C]

// ------------------------------------------------------------------
// tf32 helpers
// ------------------------------------------------------------------
__device__ __forceinline__ float f2tf32(float x) {
    unsigned r;
    asm("cvt.rna.tf32.f32 %0, %1;" : "=r"(r) : "f"(x));
    return __uint_as_float(r);
}

__device__ __forceinline__ void mma_tf32(float* c,
    unsigned a0, unsigned a1, unsigned a2, unsigned a3,
    unsigned b0, unsigned b1)
{
    asm volatile(
        "mma.sync.aligned.m16n8k8.row.col.f32.tf32.tf32.f32 "
        "{%0,%1,%2,%3}, {%4,%5,%6,%7}, {%8,%9}, {%0,%1,%2,%3};"
        : "+f"(c[0]), "+f"(c[1]), "+f"(c[2]), "+f"(c[3])
        : "r"(a0), "r"(a1), "r"(a2), "r"(a3), "r"(b0), "r"(b1));
}

// ------------------------------------------------------------------
// TF32 GEMM: C[M,N] = A[M,K] @ B[K,N], row-major fp32 in/out.
// 128x128x16 block tile, 256 threads (8 warps = 2x4), warp tile 64x32.
// Double-buffered smem. Requires M%128==0, N%128==0, K%16==0.
// ------------------------------------------------------------------
#define TBM 128
#define TBN 128
#define TBK 16
#define ASTR (TBM + 4)
#define BSTR (TBN + 4)

__global__ __launch_bounds__(256) void gemm_tf32(
    const float* __restrict__ A, const float* __restrict__ B,
    float* __restrict__ C, int M, int N, int K)
{
    __shared__ float As[2][TBK][ASTR];   // [k][m]
    __shared__ float Bs[2][TBK][BSTR];   // [k][n]

    const int tid  = threadIdx.x;
    const int lane = tid & 31;
    const int wid  = tid >> 5;
    const int wm   = (wid >> 2) << 6;   // 0 or 64
    const int wn   = (wid & 3) << 5;    // 0,32,64,96
    const int row0 = blockIdx.y * TBM;
    const int col0 = blockIdx.x * TBN;

    // global load mappings (float4)
    const int a_row = tid >> 2;          // 0..63 (and +64)
    const int a_c4  = (tid & 3) << 2;    // 0,4,8,12
    const int b_row = tid >> 5;          // 0..7 (and +8)
    const int b_c4  = (tid & 31) << 2;   // 0..124

    const int lq = lane >> 2;            // 0..7
    const int lr = lane & 3;             // 0..3

    float c[4][4][4];
    #pragma unroll
    for (int i = 0; i < 4; i++)
        #pragma unroll
        for (int j = 0; j < 4; j++)
            #pragma unroll
            for (int v = 0; v < 4; v++) c[i][j][v] = 0.f;

    const float* Ab = A + (size_t)row0 * K;
    const float* Bb = B + col0;
    const int KT = K >> 4;

    // prologue: tile 0 -> buffer 0
    {
        float4 a0 = *(const float4*)(Ab + (size_t)a_row * K + a_c4);
        float4 a1 = *(const float4*)(Ab + (size_t)(a_row + 64) * K + a_c4);
        float4 b0 = *(const float4*)(Bb + (size_t)b_row * N + b_c4);
        float4 b1 = *(const float4*)(Bb + (size_t)(b_row + 8) * N + b_c4);
        As[0][a_c4+0][a_row] = f2tf32(a0.x);
        As[0][a_c4+1][a_row] = f2tf32(a0.y);
        As[0][a_c4+2][a_row] = f2tf32(a0.z);
        As[0][a_c4+3][a_row] = f2tf32(a0.w);
        As[0][a_c4+0][a_row+64] = f2tf32(a1.x);
        As[0][a_c4+1][a_row+64] = f2tf32(a1.y);
        As[0][a_c4+2][a_row+64] = f2tf32(a1.z);
        As[0][a_c4+3][a_row+64] = f2tf32(a1.w);
        float4 tb0 = make_float4(f2tf32(b0.x), f2tf32(b0.y), f2tf32(b0.z), f2tf32(b0.w));
        float4 tb1 = make_float4(f2tf32(b1.x), f2tf32(b1.y), f2tf32(b1.z), f2tf32(b1.w));
        *(float4*)&Bs[0][b_row][b_c4]     = tb0;
        *(float4*)&Bs[0][b_row + 8][b_c4] = tb1;
    }
    __syncthreads();

    int db = 0;
    for (int kt = 0; kt < KT; kt++) {
        const bool has_next = (kt + 1) < KT;
        float4 pa0, pa1, pb0, pb1;
        if (has_next) {
            const int ko = (kt + 1) << 4;
            pa0 = *(const float4*)(Ab + (size_t)a_row * K + ko + a_c4);
            pa1 = *(const float4*)(Ab + (size_t)(a_row + 64) * K + ko + a_c4);
            pb0 = *(const float4*)(Bb + (size_t)(ko + b_row) * N + b_c4);
            pb1 = *(const float4*)(Bb + (size_t)(ko + b_row + 8) * N + b_c4);
        }

        // compute on buffer db
        #pragma unroll
        for (int ks = 0; ks < 2; ks++) {
            const int kb = ks << 3;
            unsigned aF[4][4], bF[4][2];
            #pragma unroll
            for (int mi = 0; mi < 4; mi++) {
                const int m = wm + (mi << 4) + lq;
                aF[mi][0] = __float_as_uint(As[db][kb + lr][m]);
                aF[mi][1] = __float_as_uint(As[db][kb + lr][m + 8]);
                aF[mi][2] = __float_as_uint(As[db][kb + lr + 4][m]);
                aF[mi][3] = __float_as_uint(As[db][kb + lr + 4][m + 8]);
            }
            #pragma unroll
            for (int nj = 0; nj < 4; nj++) {
                const int n = wn + (nj << 3) + lq;
                bF[nj][0] = __float_as_uint(Bs[db][kb + lr][n]);
                bF[nj][1] = __float_as_uint(Bs[db][kb + lr + 4][n]);
            }
            #pragma unroll
            for (int mi = 0; mi < 4; mi++)
                #pragma unroll
                for (int nj = 0; nj < 4; nj++)
                    mma_tf32(c[mi][nj], aF[mi][0], aF[mi][1], aF[mi][2], aF[mi][3],
                             bF[nj][0], bF[nj][1]);
        }

        if (has_next) {
            const int nb = db ^ 1;
            As[nb][a_c4+0][a_row] = f2tf32(pa0.x);
            As[nb][a_c4+1][a_row] = f2tf32(pa0.y);
            As[nb][a_c4+2][a_row] = f2tf32(pa0.z);
            As[nb][a_c4+3][a_row] = f2tf32(pa0.w);
            As[nb][a_c4+0][a_row+64] = f2tf32(pa1.x);
            As[nb][a_c4+1][a_row+64] = f2tf32(pa1.y);
            As[nb][a_c4+2][a_row+64] = f2tf32(pa1.z);
            As[nb][a_c4+3][a_row+64] = f2tf32(pa1.w);
            float4 tb0 = make_float4(f2tf32(pb0.x), f2tf32(pb0.y), f2tf32(pb0.z), f2tf32(pb0.w));
            float4 tb1 = make_float4(f2tf32(pb1.x), f2tf32(pb1.y), f2tf32(pb1.z), f2tf32(pb1.w));
            *(float4*)&Bs[nb][b_row][b_c4]     = tb0;
            *(float4*)&Bs[nb][b_row + 8][b_c4] = tb1;
        }
        __syncthreads();
        db ^= 1;
    }

    // epilogue
    #pragma unroll
    for (int mi = 0; mi < 4; mi++) {
        const int r = row0 + wm + (mi << 4) + lq;
        #pragma unroll
        for (int nj = 0; nj < 4; nj++) {
            const int cc = col0 + wn + (nj << 3) + (lr << 1);
            *(float2*)(C + (size_t)r * N + cc)       = make_float2(c[mi][nj][0], c[mi][nj][1]);
            *(float2*)(C + (size_t)(r + 8) * N + cc) = make_float2(c[mi][nj][2], c[mi][nj][3]);
        }
    }
}

// ------------------------------------------------------------------
// RoPE + transpose: qkv[B,T,3C] -> q,k,v[B,H,T,D] (rope on q,k)
// ------------------------------------------------------------------
__global__ __launch_bounds__(256) void rope_split_kernel()
{
    const long long idx = (long long)blockIdx.x * blockDim.x + threadIdx.x;
    if (idx >= (long long)BB * HH * TT * DD) return;

    const int d = (int)(idx & 63);
    const int t = (int)((idx >> 6) & 2047);
    const int h = (int)((idx >> 17) & 15);
    const int b = (int)(idx >> 21);

    const size_t base = ((size_t)(b * TT + t)) * C3 + h * DD;
    const int d2 = d ^ 32;

    const float qv = g_qkv[base + d];
    const float qp = g_qkv[base + d2];
    const float kv = g_qkv[base + CC + d];
    const float kp = g_qkv[base + CC + d2];
    const float vv = g_qkv[base + 2 * CC + d];

    const float qrot = (d < 32) ? -qp : qp;
    const float krot = (d < 32) ? -kp : kp;

    const int i = d & 31;
    const float invf = (float)exp(-(double)i / 32.0 * 9.210340371976184);
    const float angle = (float)t * invf;
    const double da = (double)angle;
    const float cs = (float)cos(da);
    const float sn = (float)sin(da);

    const size_t oidx = (((size_t)(b * HH + h)) * TT + t) * DD + d;
    g_q[oidx] = qv * cs + qrot * sn;
    g_k[oidx] = kv * cs + krot * sn;
    g_v[oidx] = vv;
}

// ------------------------------------------------------------------
// Flash attention with tf32 tensor cores. Causal, online softmax.
// Block: 128 threads (4 warps). One (b,h) head, 64-query tile.
// Warp w owns queries [16w, 16w+16). S and PV both via mma.m16n8k8.
// ------------------------------------------------------------------
#define SSTR 68

__global__ __launch_bounds__(128) void attn_tf32(
    const float* __restrict__ Q, const float* __restrict__ K,
    const float* __restrict__ V)
{
    extern __shared__ float sm[];
    float* Qs = sm;                   // [64][SSTR]  Q[q][d]   (tf32)
    float* Ks = sm + 64 * SSTR;       // [64][SSTR]  K[key][d] (tf32)
    float* Vt = Ks + 64 * SSTR;       // [64][SSTR]  V^T[d][key] (tf32)
    float* Ps = Vt + 64 * SSTR;       // [64][SSTR]  P[q][key] (tf32)

    const int tid  = threadIdx.x;
    const int lane = tid & 31;
    const int wid  = tid >> 5;
    const int wq   = wid << 4;        // warp's query offset within tile
    const int lq   = lane >> 2;       // 0..7
    const int lr   = lane & 3;        // 0..3

    const int qt = blockIdx.x;        // 0..31
    const int bh = blockIdx.y;        // 0..63
    const int q0 = qt * 64;
    const int b = bh >> 4, h = bh & 15;

    const float* Qb = Q + (size_t)bh * TT * DD;
    const float* Kb = K + (size_t)bh * TT * DD;
    const float* Vb = V + (size_t)bh * TT * DD;

    // Load Q tile (64x64): 1024 float4 slots, 8 per thread
    #pragma unroll
    for (int it = 0; it < 8; it++) {
        const int lin = tid + (it << 7);
        const int row = lin >> 4;
        const int c4  = (lin & 15) << 2;
        float4 v = *(const float4*)(Qb + (size_t)(q0 + row) * DD + c4);
        float4 t = make_float4(f2tf32(v.x), f2tf32(v.y), f2tf32(v.z), f2tf32(v.w));
        *(float4*)(Qs + row * SSTR + c4) = t;
    }

    float m_lo = -INFINITY, m_hi = -INFINITY;
    float l_lo = 0.f, l_hi = 0.f;
    float oc[8][4];
    #pragma unroll
    for (int nt = 0; nt < 8; nt++)
        #pragma unroll
        for (int v = 0; v < 4; v++) oc[nt][v] = 0.f;

    for (int kt = 0; kt <= qt; kt++) {
        const int k0 = kt * 64;
        __syncthreads();   // previous iter's smem reads done; Qs visible (1st iter)

        // Load K (natural) and V (transposed) tiles
        #pragma unroll
        for (int it = 0; it < 8; it++) {
            const int lin = tid + (it << 7);
            const int row = lin >> 4;
            const int c4  = (lin & 15) << 2;
            float4 kv = *(const float4*)(Kb + (size_t)(k0 + row) * DD + c4);
            float4 tk = make_float4(f2tf32(kv.x), f2tf32(kv.y), f2tf32(kv.z), f2tf32(kv.w));
            *(float4*)(Ks + row * SSTR + c4) = tk;
            float4 vv = *(const float4*)(Vb + (size_t)(k0 + row) * DD + c4);
            Vt[(c4 + 0) * SSTR + row] = f2tf32(vv.x);
            Vt[(c4 + 1) * SSTR + row] = f2tf32(vv.y);
            Vt[(c4 + 2) * SSTR + row] = f2tf32(vv.z);
            Vt[(c4 + 3) * SSTR + row] = f2tf32(vv.w);
        }
        __syncthreads();

        // S = Q @ K^T : 8 k-steps (d) x 8 n-tiles (keys)
        float sc[8][4];
        #pragma unroll
        for (int nt = 0; nt < 8; nt++)
            #pragma unroll
            for (int v = 0; v < 4; v++) sc[nt][v] = 0.f;

        #pragma unroll
        for (int ks = 0; ks < 8; ks++) {
            const int kk = (ks << 3) + lr;
            const int qrow = wq + lq;
            unsigned a0 = __float_as_uint(Qs[qrow * SSTR + kk]);
            unsigned a1 = __float_as_uint(Qs[(qrow + 8) * SSTR + kk]);
            unsigned a2 = __float_as_uint(Qs[qrow * SSTR + kk + 4]);
            unsigned a3 = __float_as_uint(Qs[(qrow + 8) * SSTR + kk + 4]);
            #pragma unroll
            for (int nt = 0; nt < 8; nt++) {
                const int key = (nt << 3) + lq;
                unsigned b0 = __float_as_uint(Ks[key * SSTR + kk]);
                unsigned b1 = __float_as_uint(Ks[key * SSTR + kk + 4]);
                mma_tf32(sc[nt], a0, a1, a2, a3, b0, b1);
            }
        }

        // scale + causal mask + row max (rows: lo = wq+lq, hi = +8)
        float mt_lo = -INFINITY, mt_hi = -INFINITY;
        const int row_lo = wq + lq;      // tile-local (k0 == q0 on diagonal)
        const int row_hi = row_lo + 8;
        if (kt == qt) {
            #pragma unroll
            for (int nt = 0; nt < 8; nt++) {
                const int col = (nt << 3) + (lr << 1);
                sc[nt][0] = (col     <= row_lo) ? sc[nt][0] * 0.125f : -INFINITY;
                sc[nt][1] = (col + 1 <= row_lo) ? sc[nt][1] * 0.125f : -INFINITY;
                sc[nt][2] = (col     <= row_hi) ? sc[nt][2] * 0.125f : -INFINITY;
                sc[nt][3] = (col + 1 <= row_hi) ? sc[nt][3] * 0.125f : -INFINITY;
                mt_lo = fmaxf(mt_lo, fmaxf(sc[nt][0], sc[nt][1]));
                mt_hi = fmaxf(mt_hi, fmaxf(sc[nt][2], sc[nt][3]));
            }
        } else {
            #pragma unroll
            for (int nt = 0; nt < 8; nt++) {
                sc[nt][0] *= 0.125f; sc[nt][1] *= 0.125f;
                sc[nt][2] *= 0.125f; sc[nt][3] *= 0.125f;
                mt_lo = fmaxf(mt_lo, fmaxf(sc[nt][0], sc[nt][1]));
                mt_hi = fmaxf(mt_hi, fmaxf(sc[nt][2], sc[nt][3]));
            }
        }
        mt_lo = fmaxf(mt_lo, __shfl_xor_sync(0xffffffffu, mt_lo, 1));
        mt_lo = fmaxf(mt_lo, __shfl_xor_sync(0xffffffffu, mt_lo, 2));
        mt_hi = fmaxf(mt_hi, __shfl_xor_sync(0xffffffffu, mt_hi, 1));
        mt_hi = fmaxf(mt_hi, __shfl_xor_sync(0xffffffffu, mt_hi, 2));

        const float mn_lo = fmaxf(m_lo, mt_lo);
        const float mn_hi = fmaxf(m_hi, mt_hi);
        const float al_lo = __expf(m_lo - mn_lo);
        const float al_hi = __expf(m_hi - mn_hi);

        float ls_lo = 0.f, ls_hi = 0.f;
        #pragma unroll
        for (int nt = 0; nt < 8; nt++) {
            sc[nt][0] = __expf(sc[nt][0] - mn_lo);
            sc[nt][1] = __expf(sc[nt][1] - mn_lo);
            sc[nt][2] = __expf(sc[nt][2] - mn_hi);
            sc[nt][3] = __expf(sc[nt][3] - mn_hi);
            ls_lo += sc[nt][0] + sc[nt][1];
            ls_hi += sc[nt][2] + sc[nt][3];
        }
        ls_lo += __shfl_xor_sync(0xffffffffu, ls_lo, 1);
        ls_lo += __shfl_xor_sync(0xffffffffu, ls_lo, 2);
        ls_hi += __shfl_xor_sync(0xffffffffu, ls_hi, 1);
        ls_hi += __shfl_xor_sync(0xffffffffu, ls_hi, 2);

        l_lo = l_lo * al_lo + ls_lo;
        l_hi = l_hi * al_hi + ls_hi;
        m_lo = mn_lo; m_hi = mn_hi;

        #pragma unroll
        for (int nt = 0; nt < 8; nt++) {
            oc[nt][0] *= al_lo; oc[nt][1] *= al_lo;
            oc[nt][2] *= al_hi; oc[nt][3] *= al_hi;
        }

        // stage P (tf32) into this warp's rows of Ps
        #pragma unroll
        for (int nt = 0; nt < 8; nt++) {
            const int col = (nt << 3) + (lr << 1);
            *(float2*)(Ps + (wq + lq) * SSTR + col) =
                make_float2(f2tf32(sc[nt][0]), f2tf32(sc[nt][1]));
            *(float2*)(Ps + (wq + lq + 8) * SSTR + col) =
                make_float2(f2tf32(sc[nt][2]), f2tf32(sc[nt][3]));
        }
        __syncwarp();

        // O += P @ V : 8 k-steps (keys) x 8 n-tiles (d)
        #pragma unroll
        for (int ks = 0; ks < 8; ks++) {
            const int kk = (ks << 3) + lr;
            const int qrow = wq + lq;
            unsigned a0 = __float_as_uint(Ps[qrow * SSTR + kk]);
            unsigned a1 = __float_as_uint(Ps[(qrow + 8) * SSTR + kk]);
            unsigned a2 = __float_as_uint(Ps[qrow * SSTR + kk + 4]);
            unsigned a3 = __float_as_uint(Ps[(qrow + 8) * SSTR + kk + 4]);
            #pragma unroll
            for (int nt = 0; nt < 8; nt++) {
                const int dd = (nt << 3) + lq;
                unsigned b0 = __float_as_uint(Vt[dd * SSTR + kk]);
                unsigned b1 = __float_as_uint(Vt[dd * SSTR + kk + 4]);
                mma_tf32(oc[nt], a0, a1, a2, a3, b0, b1);
            }
        }
    }

    // epilogue: normalize and write [B,T,C]
    const float inv_lo = 1.f / l_lo;
    const float inv_hi = 1.f / l_hi;
    const int t_lo = q0 + wq + lq;
    float* out_lo = g_y + ((size_t)(b * TT + t_lo)) * CC + h * DD;
    float* out_hi = g_y + ((size_t)(b * TT + t_lo + 8)) * CC + h * DD;
    #pragma unroll
    for (int nt = 0; nt < 8; nt++) {
        const int col = (nt << 3) + (lr << 1);
        *(float2*)(out_lo + col) = make_float2(oc[nt][0] * inv_lo, oc[nt][1] * inv_lo);
        *(float2*)(out_hi + col) = make_float2(oc[nt][2] * inv_hi, oc[nt][3] * inv_hi);
    }
}

// ------------------------------------------------------------------
// Launch
// ------------------------------------------------------------------
extern "C" void kernel_launch(void* const* d_in, const int* in_sizes, int n_in,
                              void* d_out, int out_size)
{
    const float* x      = (const float*)d_in[0];  // [4,2048,1024]
    const float* w_qkv  = (const float*)d_in[1];  // [1024,3072]
    const float* w_proj = (const float*)d_in[2];  // [1024,1024]
    float* out = (float*)d_out;                   // [4,2048,1024]

    float *p_qkv, *p_q, *p_k, *p_v, *p_y;
    cudaGetSymbolAddress((void**)&p_qkv, g_qkv);
    cudaGetSymbolAddress((void**)&p_q, g_q);
    cudaGetSymbolAddress((void**)&p_k, g_k);
    cudaGetSymbolAddress((void**)&p_v, g_v);
    cudaGetSymbolAddress((void**)&p_y, g_y);

    // 1. qkv = x @ w_qkv   (8192 x 3072 x 1024)
    {
        dim3 grid(C3 / TBN, MM / TBM);
        gemm_tf32<<<grid, 256>>>(x, w_qkv, p_qkv, MM, C3, CC);
    }

    // 2. rope + split into [B,H,T,D]
    {
        long long n = (long long)BB * HH * TT * DD;
        int blocks = (int)((n + 255) / 256);
        rope_split_kernel<<<blocks, 256>>>();
    }

    // 3. causal flash attention (tf32 tensor cores)
    {
        const int smem = 4 * 64 * SSTR * sizeof(float);  // 69632 B
        cudaFuncSetAttribute(attn_tf32,
                             cudaFuncAttributeMaxDynamicSharedMemorySize, smem);
        dim3 grid(TT / 64, BB * HH);
        attn_tf32<<<grid, 128, smem>>>(p_q, p_k, p_v);
    }

    // 4. out = y @ w_proj   (8192 x 1024 x 1024)
    {
        dim3 grid(CC / TBN, MM / TBM);
        gemm_tf32<<<grid, 256>>>(p_y, w_proj, out, MM, CC, CC);
    }
}

// round 3
// speedup vs baseline: 8.3732x; 3.8023x over previous
#include <cuda_runtime.h>
#include <cuda_bf16.h>
#include <math.h>

// Problem constants: B=4, T=2048, C=1024, H=16, D=64
#define BB 4
#define TT 2048
#define CC 1024
#define HH 16
#define DD 64
#define MM (BB*TT)        // 8192
#define C3 (3*CC)         // 3072

// ------------------------------------------------------------------
// Scratch
// ------------------------------------------------------------------
__device__ float g_qkv[(size_t)MM*C3];     // [B,T,3C] fp32
__device__ float g_q[(size_t)MM*CC];       // [B,H,T,D] roped, tf32
__device__ float g_k[(size_t)MM*CC];       // [B,H,T,D] roped, tf32
__device__ float g_v[(size_t)MM*CC];       // [B,H,T,D] tf32
__device__ float g_y[(size_t)MM*CC];       // attn out [B,T,C], tf32
__device__ float g_xt[(size_t)MM*CC];      // x rounded to tf32
__device__ float g_wq[(size_t)CC*C3];      // w_qkv tf32
__device__ float g_wp[(size_t)CC*CC];      // w_proj tf32
__device__ float g_cos[TT*32];
__device__ float g_sin[TT*32];

// ------------------------------------------------------------------
// helpers
// ------------------------------------------------------------------
__device__ __forceinline__ float f2tf32(float x) {
    unsigned r;
    asm("cvt.rna.tf32.f32 %0, %1;" : "=r"(r) : "f"(x));
    return __uint_as_float(r);
}

__device__ __forceinline__ void mma_tf32(float* c,
    unsigned a0, unsigned a1, unsigned a2, unsigned a3,
    unsigned b0, unsigned b1)
{
    asm volatile(
        "mma.sync.aligned.m16n8k8.row.col.f32.tf32.tf32.f32 "
        "{%0,%1,%2,%3}, {%4,%5,%6,%7}, {%8,%9}, {%0,%1,%2,%3};"
        : "+f"(c[0]), "+f"(c[1]), "+f"(c[2]), "+f"(c[3])
        : "r"(a0), "r"(a1), "r"(a2), "r"(a3), "r"(b0), "r"(b1));
}

__device__ __forceinline__ void cp16(unsigned dst, const void* src) {
    asm volatile("cp.async.cg.shared.global [%0], [%1], 16;" :: "r"(dst), "l"(src));
}
#define CP_COMMIT() asm volatile("cp.async.commit_group;")
#define CP_WAIT(N)  asm volatile("cp.async.wait_group %0;" :: "n"(N))

__device__ __forceinline__ unsigned smem_u32(const void* p) {
    return (unsigned)__cvta_generic_to_shared(p);
}

// ------------------------------------------------------------------
// Prep: elementwise tf32 rounding (float4)
// ------------------------------------------------------------------
__global__ __launch_bounds__(256) void cvt_tf32_kernel(
    const float* __restrict__ in, float* __restrict__ out, int n4)
{
    int i = blockIdx.x * blockDim.x + threadIdx.x;
    if (i >= n4) return;
    float4 v = ((const float4*)in)[i];
    v.x = f2tf32(v.x); v.y = f2tf32(v.y); v.z = f2tf32(v.z); v.w = f2tf32(v.w);
    ((float4*)out)[i] = v;
}

// ------------------------------------------------------------------
// RoPE cos/sin table, angles in float64 (matches numpy reference)
// ------------------------------------------------------------------
__global__ __launch_bounds__(256) void rope_table_kernel()
{
    int idx = blockIdx.x * blockDim.x + threadIdx.x;
    if (idx >= TT * 32) return;
    int t = idx >> 5, i = idx & 31;
    double invf = exp(-(double)i / 32.0 * 9.210340371976184);  // ln(10000)
    double da = (double)t * invf;
    g_cos[idx] = (float)cos(da);
    g_sin[idx] = (float)sin(da);
}

// ------------------------------------------------------------------
// RoPE + split: qkv[B,T,3C] -> q,k,v[B,H,T,D], tf32-rounded outputs
// ------------------------------------------------------------------
__global__ __launch_bounds__(256) void rope_split_kernel()
{
    const long long idx = (long long)blockIdx.x * blockDim.x + threadIdx.x;
    if (idx >= (long long)BB * HH * TT * DD) return;

    const int d = (int)(idx & 63);
    const int t = (int)((idx >> 6) & 2047);
    const int h = (int)((idx >> 17) & 15);
    const int b = (int)(idx >> 21);

    const size_t base = ((size_t)(b * TT + t)) * C3 + h * DD;
    const int d2 = d ^ 32;

    const float qv = g_qkv[base + d];
    const float qp = g_qkv[base + d2];
    const float kv = g_qkv[base + CC + d];
    const float kp = g_qkv[base + CC + d2];
    const float vv = g_qkv[base + 2 * CC + d];

    const float qrot = (d < 32) ? -qp : qp;
    const float krot = (d < 32) ? -kp : kp;

    const int ti = (t << 5) + (d & 31);
    const float cs = g_cos[ti];
    const float sn = g_sin[ti];

    const size_t oidx = (((size_t)(b * HH + h)) * TT + t) * DD + d;
    g_q[oidx] = f2tf32(qv * cs + qrot * sn);
    g_k[oidx] = f2tf32(kv * cs + krot * sn);
    g_v[oidx] = f2tf32(vv);
}

// ------------------------------------------------------------------
// TF32 GEMM, 4-stage cp.async pipeline.
// C[M,N] = A[M,K] @ B[K,N]; A,B already tf32-rounded fp32.
// 128x128x16 tile, 256 threads (8 warps 2x4), warp tile 64x32.
// ------------------------------------------------------------------
#define STG 4
#define ASTR 20        // 16 + 4  (A stored [m][k])
#define BSTR 136       // 128 + 8 (B stored [k][n])
#define GA_TILE (128*ASTR)
#define GB_TILE (16*BSTR)

__global__ __launch_bounds__(256, 2) void gemm_pipe(
    const float* __restrict__ A, const float* __restrict__ B,
    float* __restrict__ C, int M, int N, int K)
{
    extern __shared__ float sm[];
    float* As = sm;
    float* Bs = sm + STG * GA_TILE;

    const int tid  = threadIdx.x;
    const int lane = tid & 31;
    const int wid  = tid >> 5;
    const int wm   = (wid >> 2) << 6;
    const int wn   = (wid & 3) << 5;
    const int lq   = lane >> 2;
    const int lr   = lane & 3;
    const int row0 = blockIdx.y * 128;
    const int col0 = blockIdx.x * 128;

    const int a_row = tid >> 2;          // 0..63 (+64)
    const int a_col = (tid & 3) << 2;
    const int b_row = tid >> 5;          // 0..7 (+8)
    const int b_col = (tid & 31) << 2;

    const unsigned sA = smem_u32(As);
    const unsigned sB = smem_u32(Bs);
    const int KT = K >> 4;

    float acc[4][4][4];
    #pragma unroll
    for (int i = 0; i < 4; i++)
        #pragma unroll
        for (int j = 0; j < 4; j++)
            #pragma unroll
            for (int v = 0; v < 4; v++) acc[i][j][v] = 0.f;

    // issue tile kt into stage st
    #define GEMM_ISSUE(kt, st) do {                                            \
        const float* a0p = A + (size_t)(row0 + a_row) * K + ((kt) << 4) + a_col;\
        const float* a1p = a0p + (size_t)64 * K;                                \
        cp16(sA + (unsigned)((st)*GA_TILE + a_row*ASTR + a_col) * 4u, a0p);     \
        cp16(sA + (unsigned)((st)*GA_TILE + (a_row+64)*ASTR + a_col) * 4u, a1p);\
        const float* b0p = B + (size_t)(((kt) << 4) + b_row) * N + col0 + b_col;\
        const float* b1p = b0p + (size_t)8 * N;                                 \
        cp16(sB + (unsigned)((st)*GB_TILE + b_row*BSTR + b_col) * 4u, b0p);     \
        cp16(sB + (unsigned)((st)*GB_TILE + (b_row+8)*BSTR + b_col) * 4u, b1p); \
        CP_COMMIT();                                                            \
    } while (0)

    GEMM_ISSUE(0, 0);
    GEMM_ISSUE(1, 1);
    GEMM_ISSUE(2, 2);

    for (int kt = 0; kt < KT; kt++) {
        const int rem = KT - 1 - kt;
        if (rem >= 2)      CP_WAIT(2);
        else if (rem == 1) CP_WAIT(1);
        else               CP_WAIT(0);
        __syncthreads();
        if (kt + 3 < KT) GEMM_ISSUE(kt + 3, (kt + 3) & 3);

        const float* At = As + (kt & 3) * GA_TILE;
        const float* Bt = Bs + (kt & 3) * GB_TILE;

        #pragma unroll
        for (int kb = 0; kb < 16; kb += 8) {
            unsigned aF[4][4], bF[4][2];
            #pragma unroll
            for (int mi = 0; mi < 4; mi++) {
                const float* ap = At + (wm + (mi << 4) + lq) * ASTR + kb + lr;
                aF[mi][0] = __float_as_uint(ap[0]);
                aF[mi][1] = __float_as_uint(ap[8 * ASTR]);
                aF[mi][2] = __float_as_uint(ap[4]);
                aF[mi][3] = __float_as_uint(ap[8 * ASTR + 4]);
            }
            #pragma unroll
            for (int nj = 0; nj < 4; nj++) {
                const float* bp = Bt + (kb + lr) * BSTR + wn + (nj << 3) + lq;
                bF[nj][0] = __float_as_uint(bp[0]);
                bF[nj][1] = __float_as_uint(bp[4 * BSTR]);
            }
            #pragma unroll
            for (int mi = 0; mi < 4; mi++)
                #pragma unroll
                for (int nj = 0; nj < 4; nj++)
                    mma_tf32(acc[mi][nj], aF[mi][0], aF[mi][1], aF[mi][2], aF[mi][3],
                             bF[nj][0], bF[nj][1]);
        }
    }

    #pragma unroll
    for (int mi = 0; mi < 4; mi++) {
        const int r = row0 + wm + (mi << 4) + lq;
        #pragma unroll
        for (int nj = 0; nj < 4; nj++) {
            const int cc = col0 + wn + (nj << 3) + (lr << 1);
            *(float2*)(C + (size_t)r * N + cc)       = make_float2(acc[mi][nj][0], acc[mi][nj][1]);
            *(float2*)(C + (size_t)(r + 8) * N + cc) = make_float2(acc[mi][nj][2], acc[mi][nj][3]);
        }
    }
    #undef GEMM_ISSUE
}

// ------------------------------------------------------------------
// Flash attention, tf32 mma, cp.async double-buffered K/V.
// 128 threads (4 warps), 64-query tile, 64-key tiles.
// Inputs already tf32-rounded; output y written tf32-rounded.
// ------------------------------------------------------------------
#define QSTR 68
#define KSTR 68
#define VSTR 72

__global__ __launch_bounds__(128) void attn_pipe(
    const float* __restrict__ Q, const float* __restrict__ K,
    const float* __restrict__ V)
{
    extern __shared__ float sm[];
    float* Qs = sm;                       // [64][QSTR]
    float* Ks = Qs + 64 * QSTR;           // [2][64][KSTR]
    float* Vs = Ks + 2 * 64 * KSTR;       // [2][64][VSTR] natural [key][d]
    float* Ps = Vs + 2 * 64 * VSTR;       // [64][QSTR]

    const int tid  = threadIdx.x;
    const int lane = tid & 31;
    const int wid  = tid >> 5;
    const int wq   = wid << 4;
    const int lq   = lane >> 2;
    const int lr   = lane & 3;

    const int qt = gridDim.x - 1 - blockIdx.x;   // heavy tiles launch first
    const int bh = blockIdx.y;
    const int q0 = qt << 6;
    const int b = bh >> 4, h = bh & 15;

    const float* Qb = Q + (size_t)bh * TT * DD;
    const float* Kb = K + (size_t)bh * TT * DD;
    const float* Vb = V + (size_t)bh * TT * DD;

    const unsigned sK = smem_u32(Ks);
    const unsigned sV = smem_u32(Vs);

    #define ATTN_ISSUE(kt, buf) do {                                           \
        const float* Kp = Kb + (size_t)((kt) << 6) * DD;                        \
        const float* Vp = Vb + (size_t)((kt) << 6) * DD;                        \
        _Pragma("unroll")                                                       \
        for (int i_ = 0; i_ < 8; i_++) {                                        \
            int c_ = tid + (i_ << 7);                                           \
            int r_ = c_ >> 4, co_ = (c_ & 15) << 2;                             \
            cp16(sK + (unsigned)((buf)*64*KSTR + r_*KSTR + co_) * 4u, Kp + r_*DD + co_); \
            cp16(sV + (unsigned)((buf)*64*VSTR + r_*VSTR + co_) * 4u, Vp + r_*DD + co_); \
        }                                                                       \
        CP_COMMIT();                                                            \
    } while (0)

    ATTN_ISSUE(0, 0);

    // Q tile (raw; already tf32)
    #pragma unroll
    for (int i = 0; i < 8; i++) {
        int c = tid + (i << 7);
        int row = c >> 4, col = (c & 15) << 2;
        *(float4*)(Qs + row * QSTR + col) = *(const float4*)(Qb + (size_t)(q0 + row) * DD + col);
    }

    float m_lo = -INFINITY, m_hi = -INFINITY;
    float l_lo = 0.f, l_hi = 0.f;
    float oc[8][4];
    #pragma unroll
    for (int nt = 0; nt < 8; nt++)
        #pragma unroll
        for (int v = 0; v < 4; v++) oc[nt][v] = 0.f;

    for (int kt = 0; kt <= qt; kt++) {
        CP_WAIT(0);
        __syncthreads();
        if (kt < qt) ATTN_ISSUE(kt + 1, (kt + 1) & 1);

        const float* Kt = Ks + (kt & 1) * 64 * KSTR;
        const float* Vt = Vs + (kt & 1) * 64 * VSTR;

        // S = Q @ K^T
        float sc[8][4];
        #pragma unroll
        for (int nt = 0; nt < 8; nt++)
            #pragma unroll
            for (int v = 0; v < 4; v++) sc[nt][v] = 0.f;

        const int qrow = wq + lq;
        #pragma unroll
        for (int ks = 0; ks < 8; ks++) {
            const int kk = (ks << 3) + lr;
            unsigned a0 = __float_as_uint(Qs[qrow * QSTR + kk]);
            unsigned a1 = __float_as_uint(Qs[(qrow + 8) * QSTR + kk]);
            unsigned a2 = __float_as_uint(Qs[qrow * QSTR + kk + 4]);
            unsigned a3 = __float_as_uint(Qs[(qrow + 8) * QSTR + kk + 4]);
            #pragma unroll
            for (int nt = 0; nt < 8; nt++) {
                const int key = (nt << 3) + lq;
                unsigned b0 = __float_as_uint(Kt[key * KSTR + kk]);
                unsigned b1 = __float_as_uint(Kt[key * KSTR + kk + 4]);
                mma_tf32(sc[nt], a0, a1, a2, a3, b0, b1);
            }
        }

        // scale + causal mask + row max
        float mt_lo = -INFINITY, mt_hi = -INFINITY;
        const int row_lo = wq + lq;
        const int row_hi = row_lo + 8;
        if (kt == qt) {
            #pragma unroll
            for (int nt = 0; nt < 8; nt++) {
                const int col = (nt << 3) + (lr << 1);
                sc[nt][0] = (col     <= row_lo) ? sc[nt][0] * 0.125f : -INFINITY;
                sc[nt][1] = (col + 1 <= row_lo) ? sc[nt][1] * 0.125f : -INFINITY;
                sc[nt][2] = (col     <= row_hi) ? sc[nt][2] * 0.125f : -INFINITY;
                sc[nt][3] = (col + 1 <= row_hi) ? sc[nt][3] * 0.125f : -INFINITY;
                mt_lo = fmaxf(mt_lo, fmaxf(sc[nt][0], sc[nt][1]));
                mt_hi = fmaxf(mt_hi, fmaxf(sc[nt][2], sc[nt][3]));
            }
        } else {
            #pragma unroll
            for (int nt = 0; nt < 8; nt++) {
                sc[nt][0] *= 0.125f; sc[nt][1] *= 0.125f;
                sc[nt][2] *= 0.125f; sc[nt][3] *= 0.125f;
                mt_lo = fmaxf(mt_lo, fmaxf(sc[nt][0], sc[nt][1]));
                mt_hi = fmaxf(mt_hi, fmaxf(sc[nt][2], sc[nt][3]));
            }
        }
        mt_lo = fmaxf(mt_lo, __shfl_xor_sync(0xffffffffu, mt_lo, 1));
        mt_lo = fmaxf(mt_lo, __shfl_xor_sync(0xffffffffu, mt_lo, 2));
        mt_hi = fmaxf(mt_hi, __shfl_xor_sync(0xffffffffu, mt_hi, 1));
        mt_hi = fmaxf(mt_hi, __shfl_xor_sync(0xffffffffu, mt_hi, 2));

        const float mn_lo = fmaxf(m_lo, mt_lo);
        const float mn_hi = fmaxf(m_hi, mt_hi);
        const float al_lo = __expf(m_lo - mn_lo);
        const float al_hi = __expf(m_hi - mn_hi);

        float ls_lo = 0.f, ls_hi = 0.f;
        #pragma unroll
        for (int nt = 0; nt < 8; nt++) {
            sc[nt][0] = __expf(sc[nt][0] - mn_lo);
            sc[nt][1] = __expf(sc[nt][1] - mn_lo);
            sc[nt][2] = __expf(sc[nt][2] - mn_hi);
            sc[nt][3] = __expf(sc[nt][3] - mn_hi);
            ls_lo += sc[nt][0] + sc[nt][1];
            ls_hi += sc[nt][2] + sc[nt][3];
        }
        ls_lo += __shfl_xor_sync(0xffffffffu, ls_lo, 1);
        ls_lo += __shfl_xor_sync(0xffffffffu, ls_lo, 2);
        ls_hi += __shfl_xor_sync(0xffffffffu, ls_hi, 1);
        ls_hi += __shfl_xor_sync(0xffffffffu, ls_hi, 2);

        l_lo = l_lo * al_lo + ls_lo;
        l_hi = l_hi * al_hi + ls_hi;
        m_lo = mn_lo; m_hi = mn_hi;

        #pragma unroll
        for (int nt = 0; nt < 8; nt++) {
            oc[nt][0] *= al_lo; oc[nt][1] *= al_lo;
            oc[nt][2] *= al_hi; oc[nt][3] *= al_hi;
        }

        // stage P (tf32) — warp-private rows
        #pragma unroll
        for (int nt = 0; nt < 8; nt++) {
            const int col = (nt << 3) + (lr << 1);
            *(float2*)(Ps + qrow * QSTR + col) =
                make_float2(f2tf32(sc[nt][0]), f2tf32(sc[nt][1]));
            *(float2*)(Ps + (qrow + 8) * QSTR + col) =
                make_float2(f2tf32(sc[nt][2]), f2tf32(sc[nt][3]));
        }
        __syncwarp();

        // O += P @ V  (V natural [key][d])
        #pragma unroll
        for (int ks = 0; ks < 8; ks++) {
            const int kk = (ks << 3) + lr;
            unsigned a0 = __float_as_uint(Ps[qrow * QSTR + kk]);
            unsigned a1 = __float_as_uint(Ps[(qrow + 8) * QSTR + kk]);
            unsigned a2 = __float_as_uint(Ps[qrow * QSTR + kk + 4]);
            unsigned a3 = __float_as_uint(Ps[(qrow + 8) * QSTR + kk + 4]);
            #pragma unroll
            for (int nt = 0; nt < 8; nt++) {
                const int dd = (nt << 3) + lq;
                unsigned b0 = __float_as_uint(Vt[kk * VSTR + dd]);
                unsigned b1 = __float_as_uint(Vt[(kk + 4) * VSTR + dd]);
                mma_tf32(oc[nt], a0, a1, a2, a3, b0, b1);
            }
        }
    }

    // epilogue: normalize, round to tf32 (proj GEMM input), write [B,T,C]
    const float inv_lo = 1.f / l_lo;
    const float inv_hi = 1.f / l_hi;
    const int t_lo = q0 + wq + lq;
    float* out_lo = g_y + ((size_t)(b * TT + t_lo)) * CC + h * DD;
    float* out_hi = g_y + ((size_t)(b * TT + t_lo + 8)) * CC + h * DD;
    #pragma unroll
    for (int nt = 0; nt < 8; nt++) {
        const int col = (nt << 3) + (lr << 1);
        *(float2*)(out_lo + col) = make_float2(f2tf32(oc[nt][0] * inv_lo), f2tf32(oc[nt][1] * inv_lo));
        *(float2*)(out_hi + col) = make_float2(f2tf32(oc[nt][2] * inv_hi), f2tf32(oc[nt][3] * inv_hi));
    }
    #undef ATTN_ISSUE
}

// ------------------------------------------------------------------
// Launch
// ------------------------------------------------------------------
extern "C" void kernel_launch(void* const* d_in, const int* in_sizes, int n_in,
                              void* d_out, int out_size)
{
    const float* x      = (const float*)d_in[0];
    const float* w_qkv  = (const float*)d_in[1];
    const float* w_proj = (const float*)d_in[2];
    float* out = (float*)d_out;

    float *p_qkv, *p_q, *p_k, *p_v, *p_y, *p_xt, *p_wq, *p_wp;
    cudaGetSymbolAddress((void**)&p_qkv, g_qkv);
    cudaGetSymbolAddress((void**)&p_q, g_q);
    cudaGetSymbolAddress((void**)&p_k, g_k);
    cudaGetSymbolAddress((void**)&p_v, g_v);
    cudaGetSymbolAddress((void**)&p_y, g_y);
    cudaGetSymbolAddress((void**)&p_xt, g_xt);
    cudaGetSymbolAddress((void**)&p_wq, g_wq);
    cudaGetSymbolAddress((void**)&p_wp, g_wp);

    // 0. tf32-round GEMM inputs + rope table
    cvt_tf32_kernel<<<(MM*CC/4 + 255)/256, 256>>>(x, p_xt, MM*CC/4);
    cvt_tf32_kernel<<<(CC*C3/4 + 255)/256, 256>>>(w_qkv, p_wq, CC*C3/4);
    cvt_tf32_kernel<<<(CC*CC/4 + 255)/256, 256>>>(w_proj, p_wp, CC*CC/4);
    rope_table_kernel<<<(TT*32 + 255)/256, 256>>>();

    const int gemm_smem = STG * (GA_TILE + GB_TILE) * (int)sizeof(float);  // 75776
    cudaFuncSetAttribute(gemm_pipe,
                         cudaFuncAttributeMaxDynamicSharedMemorySize, gemm_smem);

    // 1. qkv = xt @ wq
    {
        dim3 grid(C3 / 128, MM / 128);
        gemm_pipe<<<grid, 256, gemm_smem>>>(p_xt, p_wq, p_qkv, MM, C3, CC);
    }

    // 2. rope + split (tf32 outputs)
    {
        long long n = (long long)BB * HH * TT * DD;
        rope_split_kernel<<<(int)((n + 255) / 256), 256>>>();
    }

    // 3. attention
    {
        const int smem = (64*QSTR + 2*64*KSTR + 2*64*VSTR + 64*QSTR) * (int)sizeof(float); // 106496
        cudaFuncSetAttribute(attn_pipe,
                             cudaFuncAttributeMaxDynamicSharedMemorySize, smem);
        dim3 grid(TT / 64, BB * HH);
        attn_pipe<<<grid, 128, smem>>>(p_q, p_k, p_v);
    }

    // 4. out = y @ wp
    {
        dim3 grid(CC / 128, MM / 128);
        gemm_pipe<<<grid, 256, gemm_smem>>>(p_y, p_wp, out, MM, CC, CC);
    }
}